// round 8
// baseline (speedup 1.0000x reference)
#include <cuda_runtime.h>
#include <cstdint>

// ============================================================================
// CapLayerLP PDIP QP (n=1024, m=2051): diag + rank-2 KKT -> Woodbury (2x2).
// Cluster of 8 CTAs x 128 threads (1 coord/thread), st.async+mbarrier
// push all-reduce.
//
// Round-8:
//  * mb_wait acquire scope: cluster -> cta (complete_tx already orders the
//    remote async stores into local SMEM; cluster-scope acquire on every
//    poll was UCGABAR-class overhead). Matches ptx_helpers MBARRIER_WAIT_PARITY.
//  * Fuse predictor Woodbury round into round A analytically:
//    u1 = Sum(gbase) - T0*SiD - TAB*SfD, uf = Sum(f gbase) - (T0+TAB)*SfD
//    -> 4 reduce rounds/iter (was 5). Corrector fusion NOT done (R6 showed
//    the recovered scalar chain there costs more than the round saves).
// ============================================================================

#define CL    8
#define T     128
#define NWARP 4
#define NV    1024
#define IMCON (1.0/2051.0)
#define EPSR  1e-4
#define CCAP  10.0
#define ITERS 20

__device__ __forceinline__ double wsum(double v) {
#pragma unroll
    for (int o = 16; o > 0; o >>= 1) v += __shfl_down_sync(0xffffffffu, v, o);
    return v;
}
__device__ __forceinline__ double wmaxr(double v) {
#pragma unroll
    for (int o = 16; o > 0; o >>= 1) v = fmax(v, __shfl_down_sync(0xffffffffu, v, o));
    return v;
}
__device__ __forceinline__ void wpairmax(double& n, double& d) {
#pragma unroll
    for (int o = 16; o > 0; o >>= 1) {
        double n2 = __shfl_xor_sync(0xffffffffu, n, o);
        double d2 = __shfl_xor_sync(0xffffffffu, d, o);
        if (n2 * d > n * d2) { n = n2; d = d2; }
    }
}

__device__ __forceinline__ uint32_t s2u(const void* p) {
    uint32_t a;
    asm("{ .reg .u64 t; cvta.to.shared.u64 t, %1; cvt.u32.u64 %0, t; }" : "=r"(a) : "l"(p));
    return a;
}
__device__ __forceinline__ uint32_t cta_rank() {
    uint32_t r; asm("mov.u32 %0, %%cluster_ctarank;" : "=r"(r)); return r;
}
__device__ __forceinline__ uint32_t mapa_u32(uint32_t a, uint32_t r) {
    uint32_t ra;
    asm("mapa.shared::cluster.u32 %0, %1, %2;" : "=r"(ra) : "r"(a), "r"(r));
    return ra;
}
__device__ __forceinline__ void mb_init(uint32_t a, uint32_t cnt) {
    asm volatile("mbarrier.init.shared.b64 [%0], %1;" :: "r"(a), "r"(cnt) : "memory");
}
__device__ __forceinline__ void mb_expect(uint32_t a, uint32_t bytes) {
    asm volatile("mbarrier.arrive.expect_tx.shared.b64 _, [%0], %1;"
                 :: "r"(a), "r"(bytes) : "memory");
}
// CTA-scope acquire: complete_tx orders the async-proxy remote stores into
// our SMEM before the barrier flips; cta acquire is sufficient (per the
// canonical MBARRIER_WAIT_PARITY macro).
__device__ __forceinline__ void mb_wait(uint32_t a, uint32_t ph) {
    asm volatile(
        "{\n\t.reg .pred P;\n\t"
        "WL_%=:\n\t"
        "mbarrier.try_wait.parity.acquire.cta.shared::cta.b64 P, [%0], %1, 0x989680;\n\t"
        "@P bra.uni WD_%=;\n\t"
        "bra.uni WL_%=;\n\t"
        "WD_%=:\n\t}"
        :: "r"(a), "r"(ph) : "memory");
}
__device__ __forceinline__ void st_async_d(uint32_t ra, double v, uint32_t rb) {
    asm volatile("st.async.shared::cluster.mbarrier::complete_tx::bytes.u64 [%0], %1, [%2];"
                 :: "r"(ra), "l"(__double_as_longlong(v)), "r"(rb) : "memory");
}

#define TREE4(L, s) (((L)[0][s] + (L)[1][s]) + ((L)[2][s] + (L)[3][s]))
#define TREE8(Mb, s) ((((Mb)[0][s]+(Mb)[1][s])+((Mb)[2][s]+(Mb)[3][s])) + \
                      (((Mb)[4][s]+(Mb)[5][s])+((Mb)[6][s]+(Mb)[7][s])))
#define TREE8MAX(Mb, s) fmax(fmax(fmax((Mb)[0][s],(Mb)[1][s]),fmax((Mb)[2][s],(Mb)[3][s])), \
                             fmax(fmax((Mb)[4][s],(Mb)[5][s]),fmax((Mb)[6][s],(Mb)[7][s])))

__global__ void __launch_bounds__(T, 1) __cluster_dims__(CL, 1, 1)
pdip_kernel(const float* __restrict__ xin, const int* __restrict__ male,
            float* __restrict__ out)
{
    const uint32_t rank = cta_rank();
    const int i    = threadIdx.x;
    const int lane = i & 31;
    const int wid  = i >> 5;

    __shared__ double lpart[NWARP][7];
    __shared__ double mA[CL][7], mC[CL][2], mD[CL][2], mE[CL][3], mI[CL][1];
    __shared__ __align__(8) unsigned long long mbar[5];

    const uint32_t barA = s2u(&mbar[0]);
    const uint32_t barC = s2u(&mbar[1]);
    const uint32_t barD = s2u(&mbar[2]);
    const uint32_t barE = s2u(&mbar[3]);
    const uint32_t barI = s2u(&mbar[4]);

    if (i == 0) {
        mb_init(barA, 1); mb_init(barC, 1); mb_init(barD, 1);
        mb_init(barE, 1); mb_init(barI, 1);
        mb_expect(barI, CL * 8);
        asm volatile("fence.mbarrier_init.release.cluster;" ::: "memory");
    }
    __syncthreads();
    asm volatile("barrier.cluster.arrive.aligned;" ::: "memory");
    asm volatile("barrier.cluster.wait.aligned;" ::: "memory");

    const int c = (int)rank * T + i;
    const double pi = -(double)xin[c];
    const double fi = (double)male[c];
    double xi = 0.0, s1 = 1.0, z1 = 1.0, s2 = 1.0, z2 = 1.0;

    // ---- init all-reduce: n_male ----
    {
        double v = wsum(fi);
        if (lane == 0) lpart[wid][0] = v;
        __syncthreads();
        if (wid == 0 && lane < CL) {
            double p = TREE4(lpart, 0);
            uint32_t rb = mapa_u32(barI, lane);
            uint32_t ra = mapa_u32(s2u(&mI[rank][0]), lane);
            st_async_d(ra, p, rb);
        }
        mb_wait(barI, 0);
    }
    const double nm = TREE8(mI, 0);
    const double hA = CCAP * nm / (double)NV + 1.0;
    const double hB = -(CCAP * nm / (double)NV);

    double s0 = 1.0, sA = 1.0, sB = 1.0;
    double z0 = 1.0, zA = 1.0, zB = 1.0;

    for (int it = 0; it < ITERS; ++it) {
        const uint32_t ph = (uint32_t)(it & 1);
        if (i == 0) {
            mb_expect(barA, CL*7*8);
            mb_expect(barC, CL*2*8);
            mb_expect(barD, CL*2*8);
            mb_expect(barE, CL*3*8);
        }

        // scalar reciprocals (prev-state only; overlap with round-1 vec work)
        const double inv_sss = 1.0 / (s0 * sA * sB);
        const double is0 = sA * sB * inv_sss;
        const double isA = s0 * sB * inv_sss;
        const double isB = s0 * sA * inv_sss;
        const double w0 = z0 * is0, wA = zA * isA, wB = zB * isB;
        const double M11p = s0 / z0;
        const double M22p = 1.0 / (wA + wB);

        // ============ Round 1 (fused: diag sums + predictor Woodbury) ======
        const double ss    = s1 * s2;
        const double invss = 1.0 / ss;
        const double invs1 = s2 * invss;
        const double invs2 = s1 * invss;
        const double den   = fma((double)EPSR, ss, fma(z1, s2, z2 * s1));
        const double invD  = ss / den;
        const double rp1 = s1 - xi;
        const double rp2 = xi + s2 - 1.0;
        const double w1  = z1 * invs1;
        const double w2  = z2 * invs2;
        const double rx  = EPSR*xi + pi + (z0 - z1 + z2 + fi*(zA - zB));
        const double t1v = w1*rp1 - z1;
        const double t2v = w2*rp2 - z2;
        const double gbase = -(rx - t1v + t2v) * invD;
        {
            double v0 = wsum(xi);
            double v1 = wsum(fi * xi);
            double v2 = wsum(s1 * z1 + s2 * z2);
            double v3 = wsum(invD);
            double v4 = wsum(fi * invD);
            double v5 = wsum(gbase);
            double v6 = wsum(fi * gbase);
            if (lane == 0) {
                lpart[wid][0]=v0; lpart[wid][1]=v1; lpart[wid][2]=v2;
                lpart[wid][3]=v3; lpart[wid][4]=v4; lpart[wid][5]=v5;
                lpart[wid][6]=v6;
            }
        }
        __syncthreads();
        if (wid == 0 && lane < CL) {
            uint32_t rb = mapa_u32(barA, lane);
            uint32_t ra = mapa_u32(s2u(&mA[rank][0]), lane);
            st_async_d(ra,      TREE4(lpart, 0), rb);
            st_async_d(ra + 8,  TREE4(lpart, 1), rb);
            st_async_d(ra + 16, TREE4(lpart, 2), rb);
            st_async_d(ra + 24, TREE4(lpart, 3), rb);
            st_async_d(ra + 32, TREE4(lpart, 4), rb);
            st_async_d(ra + 40, TREE4(lpart, 5), rb);
            st_async_d(ra + 48, TREE4(lpart, 6), rb);
        }
        mb_wait(barA, ph);
        const double sumx = TREE8(mA, 0);
        const double fx   = TREE8(mA, 1);
        const double szv  = TREE8(mA, 2);
        const double SiD  = TREE8(mA, 3);
        const double SfD  = TREE8(mA, 4);
        const double Sg0  = TREE8(mA, 5);
        const double Sfg0 = TREE8(mA, 6);

        const double rp0 = sumx + s0 - CCAP;
        const double rpA =  fx + sA - hA;
        const double rpB = -fx + sB - hB;
        const double SZTOT = szv + s0*z0 + sA*zA + sB*zB;
        const double mu  = SZTOT * IMCON;
        const double imu = 1.0 / mu;
        double T0 = w0*rp0 - z0;
        double TA = wA*rpA - zA;
        double TB = wB*rpB - zB;
        const double TAB = TA - TB;
        const double M11 = M11p + SiD;
        const double M22 = M22p + SfD;
        const double M12 = SfD;
        const double detinv = 1.0 / (M11*M22 - M12*M12);
        // analytic predictor Woodbury sums
        const double u1 = Sg0  - T0*SiD - TAB*SfD;
        const double uf = Sfg0 - (T0 + TAB)*SfD;
        const double Y1 = (M22*u1 - M12*uf) * detinv;
        const double Y2 = (M11*uf - M12*u1) * detinv;
        const double sdx = u1 - Y1*SiD - Y2*SfD;
        const double fdx = uf - (Y1 + Y2)*SfD;
        const double ds0 = -rp0 - sdx;
        const double dsA = -rpA - fdx;
        const double dsB = -rpB + fdx;
        const double dz0 = -z0 - w0*ds0;
        const double dzA = -zA - wA*dsA;
        const double dzB = -zB - wB*dsB;
        double sc_q = fmax(fmax(-ds0,0.0)*is0, fmax(fmax(-dsA,0.0)*isA, fmax(-dsB,0.0)*isB));
        sc_q = fmax(sc_q, fmax(1.0 + ds0*is0, 0.0));
        sc_q = fmax(sc_q, fmax(1.0 + dsA*isA, 0.0));
        sc_q = fmax(sc_q, fmax(1.0 + dsB*isB, 0.0));

        // ========= Round 2: affine dir, step max, Sum(ds dz) =============
        double prod1, prod2, g;
        {
            g = gbase - (T0 + fi*TAB) * invD;          // predictor g
            double dx  = g - (Y1 + fi*Y2) * invD;
            double ds1 = dx - rp1,  ds2 = -rp2 - dx;
            double dz1 = -z1 - w1*ds1;
            double dz2 = -z2 - w2*ds2;
            double r1 = ds1 * invs1, r2 = ds2 * invs2;
            double mq = fmax(sc_q, fmax(fmax(-r1, 0.0), fmax(-r2, 0.0)));
            mq = fmax(mq, fmax(fmax(1.0 + r1, 0.0), fmax(1.0 + r2, 0.0)));
            prod1 = ds1 * dz1;
            prod2 = ds2 * dz2;
            double v0 = wsum(prod1 + prod2);
            double v1 = wmaxr(mq);
            if (lane == 0) { lpart[wid][0] = v0; lpart[wid][1] = v1; }
        }
        __syncthreads();
        if (wid == 0 && lane < CL) {
            uint32_t rb = mapa_u32(barC, lane);
            uint32_t ra = mapa_u32(s2u(&mC[rank][0]), lane);
            st_async_d(ra,     TREE4(lpart, 0), rb);
            double mq = fmax(fmax(lpart[0][1], lpart[1][1]), fmax(lpart[2][1], lpart[3][1]));
            st_async_d(ra + 8, mq, rb);
        }
        mb_wait(barC, ph);
        const double S2v  = TREE8(mC, 0);
        const double qmax = TREE8MAX(mC, 1);

        const double aaff = (qmax > 0.0) ? fmin(1.0, 1.0 / qmax) : 1.0;
        const double S2t  = S2v + ds0*dz0 + dsA*dzA + dsB*dzB;
        const double muaff = fma(aaff*aaff, S2t, SZTOT*(1.0 - aaff)) * IMCON;
        const double smu = muaff * muaff * muaff * (imu * imu);
        const double rsz0 = s0*z0 + ds0*dz0 - smu;
        const double rszA = sA*zA + dsA*dzA - smu;
        const double rszB = sB*zB + dsB*dzB - smu;
        T0 = (z0*rp0 - rsz0) * is0;
        TA = (zA*rpA - rszA) * isA;
        TB = (zB*rpB - rszB) * isB;

        // ========= Round 3: corrector rhs + Woodbury sums ================
        const double rsz1 = s1*z1 + prod1 - smu;
        const double rsz2 = s2*z2 + prod2 - smu;
        {
            double t1 = (z1*rp1 - rsz1) * invs1;
            double t2 = (z2*rp2 - rsz2) * invs2;
            double rhs = -(rx + T0 - t1 + t2 + fi*(TA - TB));
            g = rhs * invD;
            double v0 = wsum(g);
            double v1 = wsum(fi * g);
            if (lane == 0) { lpart[wid][0] = v0; lpart[wid][1] = v1; }
        }
        __syncthreads();
        if (wid == 0 && lane < CL) {
            uint32_t rb = mapa_u32(barD, lane);
            uint32_t ra = mapa_u32(s2u(&mD[rank][0]), lane);
            st_async_d(ra,     TREE4(lpart, 0), rb);
            st_async_d(ra + 8, TREE4(lpart, 1), rb);
        }
        mb_wait(barD, ph);
        const double u1c = TREE8(mD, 0);
        const double ufc = TREE8(mD, 1);

        const double Y1c = (M22*u1c - M12*ufc) * detinv;
        const double Y2c = (M11*ufc - M12*u1c) * detinv;
        const double sdxc = u1c - Y1c*SiD - Y2c*SfD;
        const double fdxc = ufc - (Y1c + Y2c)*SfD;
        const double ds0c = -rp0 - sdxc;
        const double dsAc = -rpA - fdxc;
        const double dsBc = -rpB + fdxc;
        const double dz0c = -(rsz0 + z0*ds0c) * is0;
        const double dzAc = -(rszA + zA*dsAc) * isA;
        const double dzBc = -(rszB + zB*dsBc) * isB;
        double sc_qs = fmax(fmax(-ds0c,0.0)*is0,
                       fmax(fmax(-dsAc,0.0)*isA, fmax(-dsBc,0.0)*isB));
        double scn = fmax(-dz0c, 0.0), scd = z0;
        { double n2 = fmax(-dzAc,0.0), d2 = zA; if (n2*scd > scn*d2) { scn=n2; scd=d2; } }
        { double n2 = fmax(-dzBc,0.0), d2 = zB; if (n2*scd > scn*d2) { scn=n2; scd=d2; } }

        // ========= Round 4: corrector dir + step + update ================
        double dxc, ds1c, ds2c, dz1c, dz2c;
        {
            dxc  = g - (Y1c + fi*Y2c) * invD;
            ds1c = dxc - rp1;
            ds2c = -rp2 - dxc;
            dz1c = -(rsz1 + z1*ds1c) * invs1;
            dz2c = -(rsz2 + z2*ds2c) * invs2;
            double mqs = fmax(sc_qs, fmax(fmax(-ds1c,0.0)*invs1, fmax(-ds2c,0.0)*invs2));
            double n1 = fmax(-dz1c, 0.0), d1v = z1;
            double n2 = fmax(-dz2c, 0.0), d2v = z2;
            if (n2*d1v > n1*d2v) { n1 = n2; d1v = d2v; }
            double pn = scn, pd = scd;
            if (n1*pd > pn*d1v)  { pn = n1; pd = d1v; }
            mqs = wmaxr(mqs);
            wpairmax(pn, pd);
            if (lane == 0) { lpart[wid][0] = mqs; lpart[wid][1] = pn; lpart[wid][2] = pd; }
        }
        __syncthreads();
        if (wid == 0 && lane < CL) {
            double mq = fmax(fmax(lpart[0][0], lpart[1][0]), fmax(lpart[2][0], lpart[3][0]));
            double n1 = lpart[0][1], d1v = lpart[0][2];
            double n2 = lpart[1][1], d2v = lpart[1][2];
            if (n2*d1v > n1*d2v) { n1 = n2; d1v = d2v; }
            double n3 = lpart[2][1], d3v = lpart[2][2];
            double n4 = lpart[3][1], d4v = lpart[3][2];
            if (n4*d3v > n3*d4v) { n3 = n4; d3v = d4v; }
            if (n3*d1v > n1*d3v) { n1 = n3; d1v = d3v; }
            uint32_t rb = mapa_u32(barE, lane);
            uint32_t ra = mapa_u32(s2u(&mE[rank][0]), lane);
            st_async_d(ra,      mq,  rb);
            st_async_d(ra + 8,  n1,  rb);
            st_async_d(ra + 16, d1v, rb);
        }
        mb_wait(barE, ph);
        const double mqs = TREE8MAX(mE, 0);
        double pn, pd;
        {
            double n1 = mE[0][1], d1v = mE[0][2];
            { double n2 = mE[1][1], d2v = mE[1][2]; if (n2*d1v > n1*d2v) { n1=n2; d1v=d2v; } }
            double n3 = mE[2][1], d3v = mE[2][2];
            { double n4 = mE[3][1], d4v = mE[3][2]; if (n4*d3v > n3*d4v) { n3=n4; d3v=d4v; } }
            if (n3*d1v > n1*d3v) { n1 = n3; d1v = d3v; }
            double n5 = mE[4][1], d5v = mE[4][2];
            { double n6 = mE[5][1], d6v = mE[5][2]; if (n6*d5v > n5*d6v) { n5=n6; d5v=d6v; } }
            double n7 = mE[6][1], d7v = mE[6][2];
            { double n8 = mE[7][1], d8v = mE[7][2]; if (n8*d7v > n7*d8v) { n7=n8; d7v=d8v; } }
            if (n7*d5v > n5*d7v) { n5 = n7; d5v = d7v; }
            if (n5*d1v > n1*d5v) { n1 = n5; d1v = d5v; }
            pn = n1; pd = d1v;
        }

        if (mqs * pd > pn) { pn = mqs; pd = 1.0; }
        const double st = (pn > 0.0) ? fmin(1.0, pd / pn) : 1.0;
        const double alpha = 0.99 * st;

        s0 += alpha*ds0c;  sA += alpha*dsAc;  sB += alpha*dsBc;
        z0 += alpha*dz0c;  zA += alpha*dzAc;  zB += alpha*dzBc;
        xi += alpha*dxc;
        s1 += alpha*ds1c;  z1 += alpha*dz1c;
        s2 += alpha*ds2c;  z2 += alpha*dz2c;
    }

    out[c] = (float)xi;
}

extern "C" void kernel_launch(void* const* d_in, const int* in_sizes, int n_in,
                              void* d_out, int out_size)
{
    const float* x    = (const float*)d_in[0];
    const int*   male = (const int*)d_in[1];
    float*       out  = (float*)d_out;
    pdip_kernel<<<CL, T>>>(x, male, out);
}

// round 9
// speedup vs baseline: 8.4335x; 8.4335x over previous
#include <cuda_runtime.h>
#include <cstdint>

// ============================================================================
// CapLayerLP PDIP QP (n=1024, m=2051): diag + rank-2 KKT -> Woodbury (2x2).
// Cluster of 8 CTAs x 128 threads (1 coord/thread), st.async+mbarrier
// push all-reduce. R7 5-round structure (explicit Woodbury reductions --
// numerically safe; round count empirically free).
//
// Round-9: FULL FP32. Evidence from R6/R7/R8: per-iteration time is invariant
// to round count & sync mechanism => latency-chain-bound at a low effective
// clock. fp64 DFMA dep-latency ~64cyc, fp64 div ~350cyc; fp32 is 4 / ~25.
// Tolerance is 1e-3 and fp64 ran at 3e-17 => huge precision budget; IPM
// recomputes residuals each iteration (self-correcting).
// ============================================================================

#define CL    8
#define T     128
#define NWARP 4
#define NV    1024
#define IMCON (1.0f/2051.0f)
#define EPSR  1e-4f
#define CCAP  10.0f
#define ITERS 20

__device__ __forceinline__ float wsum(float v) {
#pragma unroll
    for (int o = 16; o > 0; o >>= 1) v += __shfl_down_sync(0xffffffffu, v, o);
    return v;
}
__device__ __forceinline__ float wmaxr(float v) {
#pragma unroll
    for (int o = 16; o > 0; o >>= 1) v = fmaxf(v, __shfl_down_sync(0xffffffffu, v, o));
    return v;
}
__device__ __forceinline__ void wpairmax(float& n, float& d) {
#pragma unroll
    for (int o = 16; o > 0; o >>= 1) {
        float n2 = __shfl_xor_sync(0xffffffffu, n, o);
        float d2 = __shfl_xor_sync(0xffffffffu, d, o);
        if (n2 * d > n * d2) { n = n2; d = d2; }
    }
}

__device__ __forceinline__ uint32_t s2u(const void* p) {
    uint32_t a;
    asm("{ .reg .u64 t; cvta.to.shared.u64 t, %1; cvt.u32.u64 %0, t; }" : "=r"(a) : "l"(p));
    return a;
}
__device__ __forceinline__ uint32_t cta_rank() {
    uint32_t r; asm("mov.u32 %0, %%cluster_ctarank;" : "=r"(r)); return r;
}
__device__ __forceinline__ uint32_t mapa_u32(uint32_t a, uint32_t r) {
    uint32_t ra;
    asm("mapa.shared::cluster.u32 %0, %1, %2;" : "=r"(ra) : "r"(a), "r"(r));
    return ra;
}
__device__ __forceinline__ void mb_init(uint32_t a, uint32_t cnt) {
    asm volatile("mbarrier.init.shared.b64 [%0], %1;" :: "r"(a), "r"(cnt) : "memory");
}
__device__ __forceinline__ void mb_expect(uint32_t a, uint32_t bytes) {
    asm volatile("mbarrier.arrive.expect_tx.shared.b64 _, [%0], %1;"
                 :: "r"(a), "r"(bytes) : "memory");
}
__device__ __forceinline__ void mb_wait(uint32_t a, uint32_t ph) {
    asm volatile(
        "{\n\t.reg .pred P;\n\t"
        "WL_%=:\n\t"
        "mbarrier.try_wait.parity.acquire.cta.shared::cta.b64 P, [%0], %1, 0x989680;\n\t"
        "@P bra.uni WD_%=;\n\t"
        "bra.uni WL_%=;\n\t"
        "WD_%=:\n\t}"
        :: "r"(a), "r"(ph) : "memory");
}
__device__ __forceinline__ void st_async_f(uint32_t ra, float v, uint32_t rb) {
    asm volatile("st.async.shared::cluster.mbarrier::complete_tx::bytes.b32 [%0], %1, [%2];"
                 :: "r"(ra), "r"(__float_as_uint(v)), "r"(rb) : "memory");
}

#define TREE4(L, s) (((L)[0][s] + (L)[1][s]) + ((L)[2][s] + (L)[3][s]))
#define TREE8(Mb, s) ((((Mb)[0][s]+(Mb)[1][s])+((Mb)[2][s]+(Mb)[3][s])) + \
                      (((Mb)[4][s]+(Mb)[5][s])+((Mb)[6][s]+(Mb)[7][s])))
#define TREE8MAX(Mb, s) fmaxf(fmaxf(fmaxf((Mb)[0][s],(Mb)[1][s]),fmaxf((Mb)[2][s],(Mb)[3][s])), \
                              fmaxf(fmaxf((Mb)[4][s],(Mb)[5][s]),fmaxf((Mb)[6][s],(Mb)[7][s])))

__global__ void __launch_bounds__(T, 1) __cluster_dims__(CL, 1, 1)
pdip_kernel(const float* __restrict__ xin, const int* __restrict__ male,
            float* __restrict__ out)
{
    const uint32_t rank = cta_rank();
    const int i    = threadIdx.x;
    const int lane = i & 31;
    const int wid  = i >> 5;

    __shared__ float lpart[NWARP][5];
    __shared__ float mA[CL][5], mB[CL][2], mC[CL][2], mD[CL][2], mE[CL][3], mI[CL][1];
    __shared__ __align__(8) unsigned long long mbar[6];

    const uint32_t barA = s2u(&mbar[0]);
    const uint32_t barB = s2u(&mbar[1]);
    const uint32_t barC = s2u(&mbar[2]);
    const uint32_t barD = s2u(&mbar[3]);
    const uint32_t barE = s2u(&mbar[4]);
    const uint32_t barI = s2u(&mbar[5]);

    if (i == 0) {
        mb_init(barA, 1); mb_init(barB, 1); mb_init(barC, 1);
        mb_init(barD, 1); mb_init(barE, 1); mb_init(barI, 1);
        mb_expect(barI, CL * 4);
        asm volatile("fence.mbarrier_init.release.cluster;" ::: "memory");
    }
    __syncthreads();
    asm volatile("barrier.cluster.arrive.aligned;" ::: "memory");
    asm volatile("barrier.cluster.wait.aligned;" ::: "memory");

    const int c = (int)rank * T + i;
    const float pi = -xin[c];
    const float fi = (float)male[c];
    float xi = 0.0f, s1 = 1.0f, z1 = 1.0f, s2 = 1.0f, z2 = 1.0f;

    // ---- init all-reduce: n_male ----
    {
        float v = wsum(fi);
        if (lane == 0) lpart[wid][0] = v;
        __syncthreads();
        if (wid == 0 && lane < CL) {
            float p = TREE4(lpart, 0);
            uint32_t rb = mapa_u32(barI, lane);
            uint32_t ra = mapa_u32(s2u(&mI[rank][0]), lane);
            st_async_f(ra, p, rb);
        }
        mb_wait(barI, 0);
    }
    const float nm = TREE8(mI, 0);
    const float hA = CCAP * nm / (float)NV + 1.0f;
    const float hB = -(CCAP * nm / (float)NV);

    float s0 = 1.0f, sA = 1.0f, sB = 1.0f;
    float z0 = 1.0f, zA = 1.0f, zB = 1.0f;

    for (int it = 0; it < ITERS; ++it) {
        const uint32_t ph = (uint32_t)(it & 1);
        if (i == 0) {
            mb_expect(barA, CL*5*4);
            mb_expect(barB, CL*2*4);
            mb_expect(barC, CL*2*4);
            mb_expect(barD, CL*2*4);
            mb_expect(barE, CL*3*4);
        }

        // scalar reciprocals (prev-state only)
        const float inv_sss = 1.0f / (s0 * sA * sB);
        const float is0 = sA * sB * inv_sss;
        const float isA = s0 * sB * inv_sss;
        const float isB = s0 * sA * inv_sss;
        const float w0 = z0 * is0, wA = zA * isA, wB = zB * isB;
        const float M11p = s0 / z0;
        const float M22p = 1.0f / (wA + wB);

        // ================= Round A: diag + residual sums =================
        const float ss    = s1 * s2;
        const float invss = 1.0f / ss;
        const float invs1 = s2 * invss;
        const float invs2 = s1 * invss;
        const float den   = fmaf(EPSR, ss, fmaf(z1, s2, z2 * s1));
        const float invD  = ss / den;
        {
            float v0 = wsum(xi);
            float v1 = wsum(fi * xi);
            float v2 = wsum(s1 * z1 + s2 * z2);
            float v3 = wsum(invD);
            float v4 = wsum(fi * invD);
            if (lane == 0) {
                lpart[wid][0]=v0; lpart[wid][1]=v1; lpart[wid][2]=v2;
                lpart[wid][3]=v3; lpart[wid][4]=v4;
            }
        }
        __syncthreads();
        if (wid == 0 && lane < CL) {
            uint32_t rb = mapa_u32(barA, lane);
            uint32_t ra = mapa_u32(s2u(&mA[rank][0]), lane);
            st_async_f(ra,      TREE4(lpart, 0), rb);
            st_async_f(ra + 4,  TREE4(lpart, 1), rb);
            st_async_f(ra + 8,  TREE4(lpart, 2), rb);
            st_async_f(ra + 12, TREE4(lpart, 3), rb);
            st_async_f(ra + 16, TREE4(lpart, 4), rb);
        }
        mb_wait(barA, ph);
        const float sumx = TREE8(mA, 0);
        const float fx   = TREE8(mA, 1);
        const float szv  = TREE8(mA, 2);
        const float SiD  = TREE8(mA, 3);
        const float SfD  = TREE8(mA, 4);

        const float rp0 = sumx + s0 - CCAP;
        const float rpA =  fx + sA - hA;
        const float rpB = -fx + sB - hB;
        const float SZTOT = szv + s0*z0 + sA*zA + sB*zB;
        const float mu  = SZTOT * IMCON;
        const float imu = 1.0f / mu;
        float T0 = w0*rp0 - z0;
        float TA = wA*rpA - zA;
        float TB = wB*rpB - zB;
        const float M11 = M11p + SiD;
        const float M22 = M22p + SfD;
        const float M12 = SfD;
        const float detinv = 1.0f / (M11*M22 - M12*M12);

        // ================= Round B: predictor rhs + Woodbury sums ========
        const float rp1 = s1 - xi;
        const float rp2 = xi + s2 - 1.0f;
        const float w1  = z1 * invs1;
        const float w2  = z2 * invs2;
        const float rx  = EPSR*xi + pi + (z0 - z1 + z2 + fi*(zA - zB));
        float g;
        {
            float rhs = -(rx + T0 - (w1*rp1 - z1) + (w2*rp2 - z2) + fi*(TA - TB));
            g = rhs * invD;
            float v0 = wsum(g);
            float v1 = wsum(fi * g);
            if (lane == 0) { lpart[wid][0] = v0; lpart[wid][1] = v1; }
        }
        __syncthreads();
        if (wid == 0 && lane < CL) {
            uint32_t rb = mapa_u32(barB, lane);
            uint32_t ra = mapa_u32(s2u(&mB[rank][0]), lane);
            st_async_f(ra,     TREE4(lpart, 0), rb);
            st_async_f(ra + 4, TREE4(lpart, 1), rb);
        }
        mb_wait(barB, ph);
        const float u1 = TREE8(mB, 0);
        const float uf = TREE8(mB, 1);

        const float Y1 = (M22*u1 - M12*uf) * detinv;
        const float Y2 = (M11*uf - M12*u1) * detinv;
        const float sdx = u1 - Y1*SiD - Y2*SfD;
        const float fdx = uf - (Y1 + Y2)*SfD;
        const float ds0 = -rp0 - sdx;
        const float dsA = -rpA - fdx;
        const float dsB = -rpB + fdx;
        const float dz0 = -z0 - w0*ds0;
        const float dzA = -zA - wA*dsA;
        const float dzB = -zB - wB*dsB;
        float sc_q = fmaxf(fmaxf(-ds0,0.0f)*is0, fmaxf(fmaxf(-dsA,0.0f)*isA, fmaxf(-dsB,0.0f)*isB));
        sc_q = fmaxf(sc_q, fmaxf(1.0f + ds0*is0, 0.0f));
        sc_q = fmaxf(sc_q, fmaxf(1.0f + dsA*isA, 0.0f));
        sc_q = fmaxf(sc_q, fmaxf(1.0f + dsB*isB, 0.0f));

        // ========= Round C: affine dir, step max, Sum(ds dz) =============
        float prod1, prod2;
        {
            float dx  = g - (Y1 + fi*Y2) * invD;
            float ds1 = dx - rp1,  ds2 = -rp2 - dx;
            float dz1 = -z1 - w1*ds1;
            float dz2 = -z2 - w2*ds2;
            float r1 = ds1 * invs1, r2 = ds2 * invs2;
            float mq = fmaxf(sc_q, fmaxf(fmaxf(-r1, 0.0f), fmaxf(-r2, 0.0f)));
            mq = fmaxf(mq, fmaxf(fmaxf(1.0f + r1, 0.0f), fmaxf(1.0f + r2, 0.0f)));
            prod1 = ds1 * dz1;
            prod2 = ds2 * dz2;
            float v0 = wsum(prod1 + prod2);
            float v1 = wmaxr(mq);
            if (lane == 0) { lpart[wid][0] = v0; lpart[wid][1] = v1; }
        }
        __syncthreads();
        if (wid == 0 && lane < CL) {
            uint32_t rb = mapa_u32(barC, lane);
            uint32_t ra = mapa_u32(s2u(&mC[rank][0]), lane);
            st_async_f(ra,     TREE4(lpart, 0), rb);
            float mq = fmaxf(fmaxf(lpart[0][1], lpart[1][1]), fmaxf(lpart[2][1], lpart[3][1]));
            st_async_f(ra + 4, mq, rb);
        }
        mb_wait(barC, ph);
        const float S2v  = TREE8(mC, 0);
        const float qmax = TREE8MAX(mC, 1);

        const float aaff = (qmax > 0.0f) ? fminf(1.0f, 1.0f / qmax) : 1.0f;
        const float S2t  = S2v + ds0*dz0 + dsA*dzA + dsB*dzB;
        const float muaff = fmaf(aaff*aaff, S2t, SZTOT*(1.0f - aaff)) * IMCON;
        const float smu = muaff * muaff * muaff * (imu * imu);
        const float rsz0 = s0*z0 + ds0*dz0 - smu;
        const float rszA = sA*zA + dsA*dzA - smu;
        const float rszB = sB*zB + dsB*dzB - smu;
        T0 = (z0*rp0 - rsz0) * is0;
        TA = (zA*rpA - rszA) * isA;
        TB = (zB*rpB - rszB) * isB;

        // ========= Round D: corrector rhs + Woodbury sums ================
        const float rsz1 = s1*z1 + prod1 - smu;
        const float rsz2 = s2*z2 + prod2 - smu;
        {
            float t1 = (z1*rp1 - rsz1) * invs1;
            float t2 = (z2*rp2 - rsz2) * invs2;
            float rhs = -(rx + T0 - t1 + t2 + fi*(TA - TB));
            g = rhs * invD;
            float v0 = wsum(g);
            float v1 = wsum(fi * g);
            if (lane == 0) { lpart[wid][0] = v0; lpart[wid][1] = v1; }
        }
        __syncthreads();
        if (wid == 0 && lane < CL) {
            uint32_t rb = mapa_u32(barD, lane);
            uint32_t ra = mapa_u32(s2u(&mD[rank][0]), lane);
            st_async_f(ra,     TREE4(lpart, 0), rb);
            st_async_f(ra + 4, TREE4(lpart, 1), rb);
        }
        mb_wait(barD, ph);
        const float u1c = TREE8(mD, 0);
        const float ufc = TREE8(mD, 1);

        const float Y1c = (M22*u1c - M12*ufc) * detinv;
        const float Y2c = (M11*ufc - M12*u1c) * detinv;
        const float sdxc = u1c - Y1c*SiD - Y2c*SfD;
        const float fdxc = ufc - (Y1c + Y2c)*SfD;
        const float ds0c = -rp0 - sdxc;
        const float dsAc = -rpA - fdxc;
        const float dsBc = -rpB + fdxc;
        const float dz0c = -(rsz0 + z0*ds0c) * is0;
        const float dzAc = -(rszA + zA*dsAc) * isA;
        const float dzBc = -(rszB + zB*dsBc) * isB;
        float sc_qs = fmaxf(fmaxf(-ds0c,0.0f)*is0,
                      fmaxf(fmaxf(-dsAc,0.0f)*isA, fmaxf(-dsBc,0.0f)*isB));
        float scn = fmaxf(-dz0c, 0.0f), scd = z0;
        { float n2 = fmaxf(-dzAc,0.0f), d2 = zA; if (n2*scd > scn*d2) { scn=n2; scd=d2; } }
        { float n2 = fmaxf(-dzBc,0.0f), d2 = zB; if (n2*scd > scn*d2) { scn=n2; scd=d2; } }

        // ========= Round E: corrector dir + step + update ================
        float dxc, ds1c, ds2c, dz1c, dz2c;
        {
            dxc  = g - (Y1c + fi*Y2c) * invD;
            ds1c = dxc - rp1;
            ds2c = -rp2 - dxc;
            dz1c = -(rsz1 + z1*ds1c) * invs1;
            dz2c = -(rsz2 + z2*ds2c) * invs2;
            float mqs = fmaxf(sc_qs, fmaxf(fmaxf(-ds1c,0.0f)*invs1, fmaxf(-ds2c,0.0f)*invs2));
            float n1 = fmaxf(-dz1c, 0.0f), d1v = z1;
            float n2 = fmaxf(-dz2c, 0.0f), d2v = z2;
            if (n2*d1v > n1*d2v) { n1 = n2; d1v = d2v; }
            float pn = scn, pd = scd;
            if (n1*pd > pn*d1v)  { pn = n1; pd = d1v; }
            mqs = wmaxr(mqs);
            wpairmax(pn, pd);
            if (lane == 0) { lpart[wid][0] = mqs; lpart[wid][1] = pn; lpart[wid][2] = pd; }
        }
        __syncthreads();
        if (wid == 0 && lane < CL) {
            float mq = fmaxf(fmaxf(lpart[0][0], lpart[1][0]), fmaxf(lpart[2][0], lpart[3][0]));
            float n1 = lpart[0][1], d1v = lpart[0][2];
            float n2 = lpart[1][1], d2v = lpart[1][2];
            if (n2*d1v > n1*d2v) { n1 = n2; d1v = d2v; }
            float n3 = lpart[2][1], d3v = lpart[2][2];
            float n4 = lpart[3][1], d4v = lpart[3][2];
            if (n4*d3v > n3*d4v) { n3 = n4; d3v = d4v; }
            if (n3*d1v > n1*d3v) { n1 = n3; d1v = d3v; }
            uint32_t rb = mapa_u32(barE, lane);
            uint32_t ra = mapa_u32(s2u(&mE[rank][0]), lane);
            st_async_f(ra,     mq,  rb);
            st_async_f(ra + 4, n1,  rb);
            st_async_f(ra + 8, d1v, rb);
        }
        mb_wait(barE, ph);
        const float mqs = TREE8MAX(mE, 0);
        float pn, pd;
        {
            float n1 = mE[0][1], d1v = mE[0][2];
            { float n2 = mE[1][1], d2v = mE[1][2]; if (n2*d1v > n1*d2v) { n1=n2; d1v=d2v; } }
            float n3 = mE[2][1], d3v = mE[2][2];
            { float n4 = mE[3][1], d4v = mE[3][2]; if (n4*d3v > n3*d4v) { n3=n4; d3v=d4v; } }
            if (n3*d1v > n1*d3v) { n1 = n3; d1v = d3v; }
            float n5 = mE[4][1], d5v = mE[4][2];
            { float n6 = mE[5][1], d6v = mE[5][2]; if (n6*d5v > n5*d6v) { n5=n6; d5v=d6v; } }
            float n7 = mE[6][1], d7v = mE[6][2];
            { float n8 = mE[7][1], d8v = mE[7][2]; if (n8*d7v > n7*d8v) { n7=n8; d7v=d8v; } }
            if (n7*d5v > n5*d7v) { n5 = n7; d5v = d7v; }
            if (n5*d1v > n1*d5v) { n1 = n5; d1v = d5v; }
            pn = n1; pd = d1v;
        }

        if (mqs * pd > pn) { pn = mqs; pd = 1.0f; }
        const float st = (pn > 0.0f) ? fminf(1.0f, pd / pn) : 1.0f;
        const float alpha = 0.99f * st;

        s0 += alpha*ds0c;  sA += alpha*dsAc;  sB += alpha*dsBc;
        z0 += alpha*dz0c;  zA += alpha*dzAc;  zB += alpha*dzBc;
        xi += alpha*dxc;
        s1 += alpha*ds1c;  z1 += alpha*dz1c;
        s2 += alpha*ds2c;  z2 += alpha*dz2c;
    }

    out[c] = xi;
}

extern "C" void kernel_launch(void* const* d_in, const int* in_sizes, int n_in,
                              void* d_out, int out_size)
{
    const float* x    = (const float*)d_in[0];
    const int*   male = (const int*)d_in[1];
    float*       out  = (float*)d_out;
    pdip_kernel<<<CL, T>>>(x, male, out);
}

// round 10
// speedup vs baseline: 9.8339x; 1.1661x over previous
#include <cuda_runtime.h>
#include <cstdint>

// ============================================================================
// CapLayerLP PDIP QP (n=1024, m=2051): diag + rank-2 KKT -> Woodbury (2x2).
// Cluster of 8 CTAs x 128 threads (1 coord/thread), st.async + mbarrier
// push all-reduce. FULL FP32 (R9: 8.4x win; rel_err 2.6e-8 << 1e-3 budget).
//
// Round-10: 5 reduce rounds/iter -> 3 via the R6 analytic RHS decomposition
// (predictor & corrector RHS are affine in the post-reduce scalars, so the
// Woodbury sums are recovered analytically). In fp64 the recovered scalar
// chain cost ~a round (R6 regressed); in fp32 it's ~20 cycles, so the fusion
// should now pay ~2 x 510ns x 20 = ~20us.
// ============================================================================

#define CL    8
#define T     128
#define NWARP 4
#define NV    1024
#define IMCON (1.0f/2051.0f)
#define EPSR  1e-4f
#define CCAP  10.0f
#define ITERS 20

__device__ __forceinline__ float wsum(float v) {
#pragma unroll
    for (int o = 16; o > 0; o >>= 1) v += __shfl_down_sync(0xffffffffu, v, o);
    return v;
}
__device__ __forceinline__ float wmaxr(float v) {
#pragma unroll
    for (int o = 16; o > 0; o >>= 1) v = fmaxf(v, __shfl_down_sync(0xffffffffu, v, o));
    return v;
}
__device__ __forceinline__ void wpairmax(float& n, float& d) {
#pragma unroll
    for (int o = 16; o > 0; o >>= 1) {
        float n2 = __shfl_xor_sync(0xffffffffu, n, o);
        float d2 = __shfl_xor_sync(0xffffffffu, d, o);
        if (n2 * d > n * d2) { n = n2; d = d2; }
    }
}

__device__ __forceinline__ uint32_t s2u(const void* p) {
    uint32_t a;
    asm("{ .reg .u64 t; cvta.to.shared.u64 t, %1; cvt.u32.u64 %0, t; }" : "=r"(a) : "l"(p));
    return a;
}
__device__ __forceinline__ uint32_t cta_rank() {
    uint32_t r; asm("mov.u32 %0, %%cluster_ctarank;" : "=r"(r)); return r;
}
__device__ __forceinline__ uint32_t mapa_u32(uint32_t a, uint32_t r) {
    uint32_t ra;
    asm("mapa.shared::cluster.u32 %0, %1, %2;" : "=r"(ra) : "r"(a), "r"(r));
    return ra;
}
__device__ __forceinline__ void mb_init(uint32_t a, uint32_t cnt) {
    asm volatile("mbarrier.init.shared.b64 [%0], %1;" :: "r"(a), "r"(cnt) : "memory");
}
__device__ __forceinline__ void mb_expect(uint32_t a, uint32_t bytes) {
    asm volatile("mbarrier.arrive.expect_tx.shared.b64 _, [%0], %1;"
                 :: "r"(a), "r"(bytes) : "memory");
}
__device__ __forceinline__ void mb_wait(uint32_t a, uint32_t ph) {
    asm volatile(
        "{\n\t.reg .pred P;\n\t"
        "WL_%=:\n\t"
        "mbarrier.try_wait.parity.acquire.cta.shared::cta.b64 P, [%0], %1, 0x989680;\n\t"
        "@P bra.uni WD_%=;\n\t"
        "bra.uni WL_%=;\n\t"
        "WD_%=:\n\t}"
        :: "r"(a), "r"(ph) : "memory");
}
__device__ __forceinline__ void st_async_f(uint32_t ra, float v, uint32_t rb) {
    asm volatile("st.async.shared::cluster.mbarrier::complete_tx::bytes.b32 [%0], %1, [%2];"
                 :: "r"(ra), "r"(__float_as_uint(v)), "r"(rb) : "memory");
}

#define TREE4(L, s) (((L)[0][s] + (L)[1][s]) + ((L)[2][s] + (L)[3][s]))
#define TREE8(Mb, s) ((((Mb)[0][s]+(Mb)[1][s])+((Mb)[2][s]+(Mb)[3][s])) + \
                      (((Mb)[4][s]+(Mb)[5][s])+((Mb)[6][s]+(Mb)[7][s])))
#define TREE8MAX(Mb, s) fmaxf(fmaxf(fmaxf((Mb)[0][s],(Mb)[1][s]),fmaxf((Mb)[2][s],(Mb)[3][s])), \
                              fmaxf(fmaxf((Mb)[4][s],(Mb)[5][s]),fmaxf((Mb)[6][s],(Mb)[7][s])))

__global__ void __launch_bounds__(T, 1) __cluster_dims__(CL, 1, 1)
pdip_kernel(const float* __restrict__ xin, const int* __restrict__ male,
            float* __restrict__ out)
{
    const uint32_t rank = cta_rank();
    const int i    = threadIdx.x;
    const int lane = i & 31;
    const int wid  = i >> 5;

    __shared__ float lpart[NWARP][7];
    __shared__ float m1[CL][7], m2[CL][6], m3[CL][3], mI[CL][1];
    __shared__ __align__(8) unsigned long long mbar[4];

    const uint32_t bar1 = s2u(&mbar[0]);
    const uint32_t bar2 = s2u(&mbar[1]);
    const uint32_t bar3 = s2u(&mbar[2]);
    const uint32_t barI = s2u(&mbar[3]);

    if (i == 0) {
        mb_init(bar1, 1); mb_init(bar2, 1); mb_init(bar3, 1); mb_init(barI, 1);
        mb_expect(barI, CL * 4);
        asm volatile("fence.mbarrier_init.release.cluster;" ::: "memory");
    }
    __syncthreads();
    asm volatile("barrier.cluster.arrive.aligned;" ::: "memory");
    asm volatile("barrier.cluster.wait.aligned;" ::: "memory");

    const int c = (int)rank * T + i;
    const float pi = -xin[c];
    const float fi = (float)male[c];
    float xi = 0.0f, s1 = 1.0f, z1 = 1.0f, s2 = 1.0f, z2 = 1.0f;

    // ---- init all-reduce: n_male ----
    {
        float v = wsum(fi);
        if (lane == 0) lpart[wid][0] = v;
        __syncthreads();
        if (wid == 0 && lane < CL) {
            float p = TREE4(lpart, 0);
            uint32_t rb = mapa_u32(barI, lane);
            uint32_t ra = mapa_u32(s2u(&mI[rank][0]), lane);
            st_async_f(ra, p, rb);
        }
        mb_wait(barI, 0);
    }
    const float nm = TREE8(mI, 0);
    const float hA = CCAP * nm / (float)NV + 1.0f;
    const float hB = -(CCAP * nm / (float)NV);

    float s0 = 1.0f, sA = 1.0f, sB = 1.0f;
    float z0 = 1.0f, zA = 1.0f, zB = 1.0f;

    for (int it = 0; it < ITERS; ++it) {
        const uint32_t ph = (uint32_t)(it & 1);
        if (i == 0) {
            mb_expect(bar1, CL*7*4);
            mb_expect(bar2, CL*6*4);
            mb_expect(bar3, CL*3*4);
        }

        // scalar reciprocals (prev-state only)
        const float inv_sss = 1.0f / (s0 * sA * sB);
        const float is0 = sA * sB * inv_sss;
        const float isA = s0 * sB * inv_sss;
        const float isB = s0 * sA * inv_sss;
        const float w0 = z0 * is0, wA = zA * isA, wB = zB * isB;
        const float M11p = s0 / z0;
        const float M22p = 1.0f / (wA + wB);

        // ================= Round 1 (fused: diag sums + predictor base) =====
        const float ss    = s1 * s2;
        const float invss = 1.0f / ss;
        const float invs1 = s2 * invss;
        const float invs2 = s1 * invss;
        const float den   = fmaf(EPSR, ss, fmaf(z1, s2, z2 * s1));
        const float invD  = ss / den;
        const float rp1 = s1 - xi;
        const float rp2 = xi + s2 - 1.0f;
        const float w1  = z1 * invs1;
        const float w2  = z2 * invs2;
        const float rx  = EPSR*xi + pi + (z0 - z1 + z2 + fi*(zA - zB));
        const float t1v = w1*rp1 - z1;
        const float t2v = w2*rp2 - z2;
        const float gbase = -(rx - t1v + t2v) * invD;
        {
            float v0 = wsum(xi);
            float v1 = wsum(fi * xi);
            float v2 = wsum(s1 * z1 + s2 * z2);
            float v3 = wsum(invD);
            float v4 = wsum(fi * invD);
            float v5 = wsum(gbase);
            float v6 = wsum(fi * gbase);
            if (lane == 0) {
                lpart[wid][0]=v0; lpart[wid][1]=v1; lpart[wid][2]=v2;
                lpart[wid][3]=v3; lpart[wid][4]=v4; lpart[wid][5]=v5;
                lpart[wid][6]=v6;
            }
        }
        __syncthreads();
        if (wid == 0 && lane < CL) {
            uint32_t rb = mapa_u32(bar1, lane);
            uint32_t ra = mapa_u32(s2u(&m1[rank][0]), lane);
            st_async_f(ra,      TREE4(lpart, 0), rb);
            st_async_f(ra + 4,  TREE4(lpart, 1), rb);
            st_async_f(ra + 8,  TREE4(lpart, 2), rb);
            st_async_f(ra + 12, TREE4(lpart, 3), rb);
            st_async_f(ra + 16, TREE4(lpart, 4), rb);
            st_async_f(ra + 20, TREE4(lpart, 5), rb);
            st_async_f(ra + 24, TREE4(lpart, 6), rb);
        }
        mb_wait(bar1, ph);
        const float sumx = TREE8(m1, 0);
        const float fx   = TREE8(m1, 1);
        const float szv  = TREE8(m1, 2);
        const float SiD  = TREE8(m1, 3);
        const float SfD  = TREE8(m1, 4);
        const float Sg0  = TREE8(m1, 5);
        const float Sfg0 = TREE8(m1, 6);

        // post-round-1 scalar algebra
        const float rp0 = sumx + s0 - CCAP;
        const float rpA =  fx + sA - hA;
        const float rpB = -fx + sB - hB;
        const float SZTOT = szv + s0*z0 + sA*zA + sB*zB;
        const float mu  = SZTOT * IMCON;
        const float imu = 1.0f / mu;
        const float T0 = w0*rp0 - z0;
        const float TA = wA*rpA - zA;
        const float TB = wB*rpB - zB;
        const float TAB = TA - TB;
        const float M11 = M11p + SiD;
        const float M22 = M22p + SfD;
        const float M12 = SfD;
        const float detinv = 1.0f / (M11*M22 - M12*M12);
        const float u1 = Sg0  - T0*SiD - TAB*SfD;           // analytic Sum(g)
        const float uf = Sfg0 - (T0 + TAB)*SfD;             // analytic Sum(f g)
        const float Y1 = (M22*u1 - M12*uf) * detinv;
        const float Y2 = (M11*uf - M12*u1) * detinv;
        const float sdx = u1 - Y1*SiD - Y2*SfD;
        const float fdx = uf - (Y1 + Y2)*SfD;
        const float ds0 = -rp0 - sdx;
        const float dsA = -rpA - fdx;
        const float dsB = -rpB + fdx;
        const float dz0 = -z0 - w0*ds0;
        const float dzA = -zA - wA*dsA;
        const float dzB = -zB - wB*dsB;
        float sc_q = fmaxf(fmaxf(-ds0,0.0f)*is0, fmaxf(fmaxf(-dsA,0.0f)*isA, fmaxf(-dsB,0.0f)*isB));
        sc_q = fmaxf(sc_q, fmaxf(1.0f + ds0*is0, 0.0f));
        sc_q = fmaxf(sc_q, fmaxf(1.0f + dsA*isA, 0.0f));
        sc_q = fmaxf(sc_q, fmaxf(1.0f + dsB*isB, 0.0f));

        // ========= Round 2 (fused: affine step/mu_aff + corrector base) ====
        float prod1, prod2, gcb, cw;
        {
            float g  = gbase - (T0 + fi*TAB) * invD;         // predictor g
            float dx = g - (Y1 + fi*Y2) * invD;              // affine dir
            float ds1 = dx - rp1,  ds2 = -rp2 - dx;
            float dz1 = -z1 - w1*ds1;
            float dz2 = -z2 - w2*ds2;
            float r1 = ds1 * invs1, r2 = ds2 * invs2;
            float mq = fmaxf(sc_q, fmaxf(fmaxf(-r1, 0.0f), fmaxf(-r2, 0.0f)));
            mq = fmaxf(mq, fmaxf(fmaxf(1.0f + r1, 0.0f), fmaxf(1.0f + r2, 0.0f)));
            prod1 = ds1 * dz1;
            prod2 = ds2 * dz2;
            // corrector base with smu/T0c/TABc factored out analytically
            float t1b = (z1*rp1 - s1*z1 - prod1) * invs1;
            float t2b = (z2*rp2 - s2*z2 - prod2) * invs2;
            gcb = -(rx + t2b - t1b) * invD;
            cw  = (invs2 - invs1) * invD;
            float v0 = wsum(prod1 + prod2);
            float v1 = wmaxr(mq);
            float v2 = wsum(gcb);
            float v3 = wsum(fi * gcb);
            float v4 = wsum(cw);
            float v5 = wsum(fi * cw);
            if (lane == 0) {
                lpart[wid][0]=v0; lpart[wid][1]=v1; lpart[wid][2]=v2;
                lpart[wid][3]=v3; lpart[wid][4]=v4; lpart[wid][5]=v5;
            }
        }
        __syncthreads();
        if (wid == 0 && lane < CL) {
            uint32_t rb = mapa_u32(bar2, lane);
            uint32_t ra = mapa_u32(s2u(&m2[rank][0]), lane);
            st_async_f(ra,      TREE4(lpart, 0), rb);
            float mq = fmaxf(fmaxf(lpart[0][1], lpart[1][1]), fmaxf(lpart[2][1], lpart[3][1]));
            st_async_f(ra + 4,  mq, rb);
            st_async_f(ra + 8,  TREE4(lpart, 2), rb);
            st_async_f(ra + 12, TREE4(lpart, 3), rb);
            st_async_f(ra + 16, TREE4(lpart, 4), rb);
            st_async_f(ra + 20, TREE4(lpart, 5), rb);
        }
        mb_wait(bar2, ph);
        const float S2v  = TREE8(m2, 0);
        const float qmax = TREE8MAX(m2, 1);
        const float Sgc  = TREE8(m2, 2);
        const float Sfgc = TREE8(m2, 3);
        const float Scw  = TREE8(m2, 4);
        const float Sfcw = TREE8(m2, 5);

        // post-round-2 scalar algebra
        const float aaff = (qmax > 0.0f) ? fminf(1.0f, 1.0f / qmax) : 1.0f;
        const float S2t  = S2v + ds0*dz0 + dsA*dzA + dsB*dzB;
        const float muaff = fmaf(aaff*aaff, S2t, SZTOT*(1.0f - aaff)) * IMCON;
        const float smu = muaff * muaff * muaff * (imu * imu);
        const float rsz0 = s0*z0 + ds0*dz0 - smu;
        const float rszA = sA*zA + dsA*dzA - smu;
        const float rszB = sB*zB + dsB*dzB - smu;
        const float T0c = (z0*rp0 - rsz0) * is0;
        const float TAc = (zA*rpA - rszA) * isA;
        const float TBc = (zB*rpB - rszB) * isB;
        const float TABc = TAc - TBc;
        const float u1c = Sgc  - T0c*SiD - TABc*SfD - smu*Scw;
        const float ufc = Sfgc - (T0c + TABc)*SfD   - smu*Sfcw;
        const float Y1c = (M22*u1c - M12*ufc) * detinv;
        const float Y2c = (M11*ufc - M12*u1c) * detinv;
        const float sdxc = u1c - Y1c*SiD - Y2c*SfD;
        const float fdxc = ufc - (Y1c + Y2c)*SfD;
        const float ds0c = -rp0 - sdxc;
        const float dsAc = -rpA - fdxc;
        const float dsBc = -rpB + fdxc;
        const float dz0c = -(rsz0 + z0*ds0c) * is0;
        const float dzAc = -(rszA + zA*dsAc) * isA;
        const float dzBc = -(rszB + zB*dsBc) * isB;
        float sc_qs = fmaxf(fmaxf(-ds0c,0.0f)*is0,
                      fmaxf(fmaxf(-dsAc,0.0f)*isA, fmaxf(-dsBc,0.0f)*isB));
        float scn = fmaxf(-dz0c, 0.0f), scd = z0;
        { float n2 = fmaxf(-dzAc,0.0f), d2 = zA; if (n2*scd > scn*d2) { scn=n2; scd=d2; } }
        { float n2 = fmaxf(-dzBc,0.0f), d2 = zB; if (n2*scd > scn*d2) { scn=n2; scd=d2; } }

        // ================= Round 3 (corrector dir + step) =================
        float dxc, ds1c, ds2c, dz1c, dz2c;
        const float rsz1 = s1*z1 + prod1 - smu;
        const float rsz2 = s2*z2 + prod2 - smu;
        {
            float gc = gcb - (T0c + fi*TABc)*invD - smu*cw;   // corrector g
            dxc  = gc - (Y1c + fi*Y2c) * invD;
            ds1c = dxc - rp1;
            ds2c = -rp2 - dxc;
            dz1c = -(rsz1 + z1*ds1c) * invs1;
            dz2c = -(rsz2 + z2*ds2c) * invs2;
            float mqs = fmaxf(sc_qs, fmaxf(fmaxf(-ds1c,0.0f)*invs1, fmaxf(-ds2c,0.0f)*invs2));
            float n1 = fmaxf(-dz1c, 0.0f), d1v = z1;
            float n2 = fmaxf(-dz2c, 0.0f), d2v = z2;
            if (n2*d1v > n1*d2v) { n1 = n2; d1v = d2v; }
            float pn = scn, pd = scd;
            if (n1*pd > pn*d1v)  { pn = n1; pd = d1v; }
            mqs = wmaxr(mqs);
            wpairmax(pn, pd);
            if (lane == 0) { lpart[wid][0] = mqs; lpart[wid][1] = pn; lpart[wid][2] = pd; }
        }
        __syncthreads();
        if (wid == 0 && lane < CL) {
            float mq = fmaxf(fmaxf(lpart[0][0], lpart[1][0]), fmaxf(lpart[2][0], lpart[3][0]));
            float n1 = lpart[0][1], d1v = lpart[0][2];
            float n2 = lpart[1][1], d2v = lpart[1][2];
            if (n2*d1v > n1*d2v) { n1 = n2; d1v = d2v; }
            float n3 = lpart[2][1], d3v = lpart[2][2];
            float n4 = lpart[3][1], d4v = lpart[3][2];
            if (n4*d3v > n3*d4v) { n3 = n4; d3v = d4v; }
            if (n3*d1v > n1*d3v) { n1 = n3; d1v = d3v; }
            uint32_t rb = mapa_u32(bar3, lane);
            uint32_t ra = mapa_u32(s2u(&m3[rank][0]), lane);
            st_async_f(ra,     mq,  rb);
            st_async_f(ra + 4, n1,  rb);
            st_async_f(ra + 8, d1v, rb);
        }
        mb_wait(bar3, ph);
        const float mqs = TREE8MAX(m3, 0);
        float pn, pd;
        {
            float n1 = m3[0][1], d1v = m3[0][2];
            { float n2 = m3[1][1], d2v = m3[1][2]; if (n2*d1v > n1*d2v) { n1=n2; d1v=d2v; } }
            float n3 = m3[2][1], d3v = m3[2][2];
            { float n4 = m3[3][1], d4v = m3[3][2]; if (n4*d3v > n3*d4v) { n3=n4; d3v=d4v; } }
            if (n3*d1v > n1*d3v) { n1 = n3; d1v = d3v; }
            float n5 = m3[4][1], d5v = m3[4][2];
            { float n6 = m3[5][1], d6v = m3[5][2]; if (n6*d5v > n5*d6v) { n5=n6; d5v=d6v; } }
            float n7 = m3[6][1], d7v = m3[6][2];
            { float n8 = m3[7][1], d8v = m3[7][2]; if (n8*d7v > n7*d8v) { n7=n8; d7v=d8v; } }
            if (n7*d5v > n5*d7v) { n5 = n7; d5v = d7v; }
            if (n5*d1v > n1*d5v) { n1 = n5; d1v = d5v; }
            pn = n1; pd = d1v;
        }

        if (mqs * pd > pn) { pn = mqs; pd = 1.0f; }
        const float st = (pn > 0.0f) ? fminf(1.0f, pd / pn) : 1.0f;
        const float alpha = 0.99f * st;

        s0 += alpha*ds0c;  sA += alpha*dsAc;  sB += alpha*dsBc;
        z0 += alpha*dz0c;  zA += alpha*dzAc;  zB += alpha*dzBc;
        xi += alpha*dxc;
        s1 += alpha*ds1c;  z1 += alpha*dz1c;
        s2 += alpha*ds2c;  z2 += alpha*dz2c;
    }

    out[c] = xi;
}

extern "C" void kernel_launch(void* const* d_in, const int* in_sizes, int n_in,
                              void* d_out, int out_size)
{
    const float* x    = (const float*)d_in[0];
    const int*   male = (const int*)d_in[1];
    float*       out  = (float*)d_out;
    pdip_kernel<<<CL, T>>>(x, male, out);
}